// round 2
// baseline (speedup 1.0000x reference)
#include <cuda_runtime.h>

#define BATCH 16
#define NN    1024
#define DD    64
#define EPSF      0.1f
#define INV_EPS   10.0f
#define LOG_MU   (-6.9314616f)   // log(1/1024 + 1e-8)
#define THRESH    0.1f
#define MAX_ITER  100

// ---------------- device scratch (static: no allocations allowed) ----------------
__device__ float g_K [BATCH * NN * NN];   // 64 MB: K = exp(-C/eps), L2-resident
__device__ float g_xs[BATCH * NN * DD];
__device__ float g_ys[BATCH * NN * DD];
__device__ float g_x2[BATCH * NN];
__device__ float g_y2[BATCH * NN];
__device__ float g_u [BATCH * NN];
__device__ float g_v [BATCH * NN];
__device__ float g_a [BATCH * NN];        // exp(u/eps)
__device__ float g_b [BATCH * NN];        // exp(v/eps)
__device__ float g_err[BATCH];
__device__ int    g_done;
__device__ int    g_ctr;
__device__ double g_cost;

// ---------------- softmax over last dim (D=64), one warp per row ----------------
__global__ void softmax_kernel(const float* __restrict__ x, const float* __restrict__ y) {
    int gwarp = (blockIdx.x * blockDim.x + threadIdx.x) >> 5;
    int lane  = threadIdx.x & 31;
    const float* src; float* dst; float* nrm; int row;
    if (gwarp < BATCH * NN) { src = x; dst = g_xs; nrm = g_x2; row = gwarp; }
    else                    { src = y; dst = g_ys; nrm = g_y2; row = gwarp - BATCH * NN; }
    const float* r = src + row * DD;
    float e0 = r[lane], e1 = r[lane + 32];
    float m = fmaxf(e0, e1);
    #pragma unroll
    for (int o = 16; o; o >>= 1) m = fmaxf(m, __shfl_xor_sync(0xFFFFFFFFu, m, o));
    float s0 = __expf(e0 - m), s1 = __expf(e1 - m);
    float s = s0 + s1;
    #pragma unroll
    for (int o = 16; o; o >>= 1) s += __shfl_xor_sync(0xFFFFFFFFu, s, o);
    float inv = 1.0f / s;
    float p0 = s0 * inv, p1 = s1 * inv;
    float* d = dst + row * DD;
    d[lane] = p0; d[lane + 32] = p1;
    float q = p0 * p0 + p1 * p1;
    #pragma unroll
    for (int o = 16; o; o >>= 1) q += __shfl_xor_sync(0xFFFFFFFFu, q, o);
    if (lane == 0) nrm[row] = q;
}

// ---------------- init per launch (deterministic across graph replays) ----------------
__global__ void init_kernel() {
    int idx = blockIdx.x * blockDim.x + threadIdx.x;
    if (idx < BATCH * NN) { g_u[idx] = 0.f; g_v[idx] = 0.f; g_a[idx] = 1.f; g_b[idx] = 1.f; }
    if (idx < BATCH)       g_err[idx] = 0.f;
    if (idx == 0) { g_done = 0; g_ctr = 0; g_cost = 0.0; }
}

// ---------------- K = exp((2 x.y - |x|^2 - |y|^2)/eps), 64x64 tiles ----------------
__global__ void buildK_kernel() {
    __shared__ float As[64][65];
    __shared__ float Bs[64][65];
    __shared__ float x2s[64], y2s[64];
    int bx = blockIdx.x;
    int batch = bx >> 8;
    int tile  = bx & 255;
    int i0 = (tile >> 4) * 64, j0 = (tile & 15) * 64;
    int t = threadIdx.x;
    const float* xsrc = g_xs + (batch * NN + i0) * DD;
    const float* ysrc = g_ys + (batch * NN + j0) * DD;
    #pragma unroll
    for (int k = 0; k < 16; k++) {
        int lin = k * 256 + t;
        As[lin >> 6][lin & 63] = xsrc[lin];
        Bs[lin >> 6][lin & 63] = ysrc[lin];
    }
    if (t < 64) { x2s[t] = g_x2[batch * NN + i0 + t]; y2s[t] = g_y2[batch * NN + j0 + t]; }
    __syncthreads();
    int tx = t & 15, ty = t >> 4;
    float acc[4][4];
    #pragma unroll
    for (int a = 0; a < 4; a++)
        #pragma unroll
        for (int b = 0; b < 4; b++) acc[a][b] = 0.f;
    #pragma unroll
    for (int d = 0; d < 64; d++) {
        float av[4], bv[4];
        #pragma unroll
        for (int ii = 0; ii < 4; ii++) av[ii] = As[ty + ii * 16][d];
        #pragma unroll
        for (int jj = 0; jj < 4; jj++) bv[jj] = Bs[tx + jj * 16][d];
        #pragma unroll
        for (int ii = 0; ii < 4; ii++)
            #pragma unroll
            for (int jj = 0; jj < 4; jj++) acc[ii][jj] += av[ii] * bv[jj];
    }
    float* Kb = g_K + batch * NN * NN;
    #pragma unroll
    for (int ii = 0; ii < 4; ii++) {
        int i = i0 + ty + ii * 16;
        float xi2 = x2s[ty + ii * 16];
        #pragma unroll
        for (int jj = 0; jj < 4; jj++) {
            int j = j0 + tx + jj * 16;
            float m = (2.0f * acc[ii][jj] - xi2 - y2s[tx + jj * 16]) * INV_EPS;
            Kb[i * NN + j] = __expf(m);
        }
    }
}

// ---------------- u-update: r_i = sum_j K_ij b_j ; warp per row ----------------
__global__ void row_kernel() {
    if (g_done) return;
    int batch = blockIdx.x >> 7;       // 128 blocks per batch
    int rg    = blockIdx.x & 127;      // 8 rows each
    __shared__ float4 bs[256];
    __shared__ float  du_sh[8];
    const float4* bvec = (const float4*)(g_b + batch * NN);
    bs[threadIdx.x] = bvec[threadIdx.x];
    __syncthreads();
    int w = threadIdx.x >> 5, lane = threadIdx.x & 31;
    int i = rg * 8 + w;
    const float4* Kr = (const float4*)(g_K + (batch * NN + i) * NN);
    float sum = 0.f;
    #pragma unroll
    for (int k = 0; k < 8; k++) {
        float4 kv = Kr[k * 32 + lane];
        float4 bv = bs[k * 32 + lane];
        sum += kv.x * bv.x + kv.y * bv.y + kv.z * bv.z + kv.w * bv.w;
    }
    #pragma unroll
    for (int o = 16; o; o >>= 1) sum += __shfl_xor_sync(0xFFFFFFFFu, sum, o);
    if (lane == 0) {
        int gi = batch * NN + i;
        float uo = g_u[gi];
        float a  = g_a[gi];
        float lse = logf(fmaf(a, sum, 1e-6f));     // accurate log: iteration-count fidelity
        float un  = EPSF * (LOG_MU - lse) + uo;
        g_u[gi] = un;
        g_a[gi] = expf(un * INV_EPS);
        du_sh[w] = fabsf(un - uo);
    }
    __syncthreads();
    if (threadIdx.x == 0) {
        float d = 0.f;
        #pragma unroll
        for (int k = 0; k < 8; k++) d += du_sh[k];
        atomicAdd(&g_err[batch], d);
    }
}

// ---------------- v-update: s_j = sum_i K_ij a_i ; coalesced column tiles ----------------
__global__ void col_kernel() {
    if (g_done) return;
    int batch = blockIdx.x >> 3;       // 8 j-tiles of 128 per batch
    int jt    = blockIdx.x & 7;
    __shared__ float a_sh[NN];
    __shared__ float psum[512];
    int t = threadIdx.x;
    ((float2*)a_sh)[t] = ((const float2*)(g_a + batch * NN))[t];
    __syncthreads();
    int tx = t & 127, ig = t >> 7;     // 4 i-groups of 256 rows
    int j = jt * 128 + tx;
    const float* Kc = g_K + (batch * NN + ig * 256) * NN + j;
    const float* as = a_sh + ig * 256;
    float sum = 0.f;
    #pragma unroll 8
    for (int i = 0; i < 256; i++) sum += Kc[i * NN] * as[i];
    psum[t] = sum;
    __syncthreads();
    if (t < 128) {
        float s = psum[t] + psum[t + 128] + psum[t + 256] + psum[t + 384];
        int gj = batch * NN + j;
        float vo = g_v[gj], b = g_b[gj];
        float lse = logf(fmaf(b, s, 1e-6f));
        float vn  = EPSF * (LOG_MU - lse) + vo;
        g_v[gj] = vn;
        g_b[gj] = expf(vn * INV_EPS);
    }
    // last finished block evaluates the while-loop condition for next iteration
    if (t == 0) {
        __threadfence();
        int ticket = atomicAdd(&g_ctr, 1);
        if (ticket == (int)gridDim.x - 1) {
            float e = 0.f;
            #pragma unroll
            for (int bb = 0; bb < BATCH; bb++) { e += g_err[bb]; g_err[bb] = 0.f; }
            if (e * (1.0f / BATCH) < THRESH) g_done = 1;
            g_ctr = 0;
        }
    }
}

// ---------------- cost = mean_b sum_ij a_i b_j K_ij * (-eps ln K_ij) ----------------
__global__ void cost_kernel() {
    int batch = blockIdx.x >> 7;
    int rg    = blockIdx.x & 127;
    __shared__ float4 bs[256];
    __shared__ float  rsum[8];
    const float4* bvec = (const float4*)(g_b + batch * NN);
    bs[threadIdx.x] = bvec[threadIdx.x];
    __syncthreads();
    int w = threadIdx.x >> 5, lane = threadIdx.x & 31;
    int i = rg * 8 + w;
    const float4* Kr = (const float4*)(g_K + (batch * NN + i) * NN);
    float sum = 0.f;
    #pragma unroll
    for (int k = 0; k < 8; k++) {
        float4 kv = Kr[k * 32 + lane];
        float4 bv = bs[k * 32 + lane];
        sum += kv.x * bv.x * __logf(kv.x);
        sum += kv.y * bv.y * __logf(kv.y);
        sum += kv.z * bv.z * __logf(kv.z);
        sum += kv.w * bv.w * __logf(kv.w);
    }
    #pragma unroll
    for (int o = 16; o; o >>= 1) sum += __shfl_xor_sync(0xFFFFFFFFu, sum, o);
    if (lane == 0) rsum[w] = g_a[batch * NN + i] * sum;
    __syncthreads();
    if (threadIdx.x == 0) {
        float bsum = 0.f;
        #pragma unroll
        for (int k = 0; k < 8; k++) bsum += rsum[k];
        atomicAdd(&g_cost, (double)(-EPSF * bsum));
    }
}

__global__ void finalize_kernel(float* out) {
    out[0] = (float)(g_cost * (1.0 / (double)BATCH));
}

// ---------------- launch ----------------
extern "C" void kernel_launch(void* const* d_in, const int* in_sizes, int n_in,
                              void* d_out, int out_size) {
    const float* x = (const float*)d_in[0];
    const float* y = (const float*)d_in[1];
    float* out = (float*)d_out;
    (void)in_sizes; (void)n_in; (void)out_size;

    softmax_kernel<<<4096, 256>>>(x, y);   // 32768 rows, warp per row
    init_kernel<<<64, 256>>>();
    buildK_kernel<<<4096, 256>>>();        // 16 batches x 256 tiles of 64x64

    for (int it = 0; it < MAX_ITER; it++) {
        row_kernel<<<2048, 256>>>();       // guarded by g_done
        col_kernel<<<128, 512>>>();        // guarded; tail evaluates exit condition
    }

    cost_kernel<<<2048, 256>>>();
    finalize_kernel<<<1, 1>>>(out);
}

// round 3
// speedup vs baseline: 3.7024x; 3.7024x over previous
#include <cuda_runtime.h>

#define BATCH 16
#define NN    1024
#define DD    64
#define EPSF      0.1f
#define INV_EPS   10.0f
#define LOG_MU   (-6.9314616f)   // log(1/1024 + 1e-8)
#define THRESH    0.1f
#define MAX_ITER  100
#define GB        128            // persistent grid: 128 blocks (<= 148 SMs, all co-resident)
#define TB        1024

// ---------------- device scratch (static: no allocations allowed) ----------------
__device__ float g_K [BATCH * NN * NN];   // 64 MB: K = exp(-C/eps), L2-resident
__device__ float g_xs[BATCH * NN * DD];
__device__ float g_ys[BATCH * NN * DD];
__device__ float g_x2[BATCH * NN];
__device__ float g_y2[BATCH * NN];
__device__ float g_u [BATCH * NN];
__device__ float g_v [BATCH * NN];
__device__ float g_a [BATCH * NN];        // exp(u/eps)
__device__ float g_b [BATCH * NN];        // exp(v/eps)
__device__ float g_errA[MAX_ITER * BATCH];// per-iteration err slots (no reset races)
__device__ double   g_cost;
__device__ unsigned g_bar_cnt;
__device__ unsigned g_bar_gen;

// ---------------- software grid barrier (all GB blocks co-resident) ----------------
__device__ __forceinline__ void grid_barrier() {
    __threadfence();
    __syncthreads();
    if (threadIdx.x == 0) {
        unsigned gen = *((volatile unsigned*)&g_bar_gen);
        if (atomicAdd(&g_bar_cnt, 1u) == GB - 1u) {
            g_bar_cnt = 0u;
            __threadfence();
            *((volatile unsigned*)&g_bar_gen) = gen + 1u;
        } else {
            while (*((volatile unsigned*)&g_bar_gen) == gen) { __nanosleep(64); }
        }
    }
    __syncthreads();
}

// ---------------- softmax over last dim (D=64), one warp per row ----------------
__global__ void softmax_kernel(const float* __restrict__ x, const float* __restrict__ y) {
    int gwarp = (blockIdx.x * blockDim.x + threadIdx.x) >> 5;
    int lane  = threadIdx.x & 31;
    const float* src; float* dst; float* nrm; int row;
    if (gwarp < BATCH * NN) { src = x; dst = g_xs; nrm = g_x2; row = gwarp; }
    else                    { src = y; dst = g_ys; nrm = g_y2; row = gwarp - BATCH * NN; }
    const float* r = src + row * DD;
    float e0 = r[lane], e1 = r[lane + 32];
    float m = fmaxf(e0, e1);
    #pragma unroll
    for (int o = 16; o; o >>= 1) m = fmaxf(m, __shfl_xor_sync(0xFFFFFFFFu, m, o));
    float s0 = __expf(e0 - m), s1 = __expf(e1 - m);
    float s = s0 + s1;
    #pragma unroll
    for (int o = 16; o; o >>= 1) s += __shfl_xor_sync(0xFFFFFFFFu, s, o);
    float inv = 1.0f / s;
    float p0 = s0 * inv, p1 = s1 * inv;
    float* d = dst + row * DD;
    d[lane] = p0; d[lane + 32] = p1;
    float q = p0 * p0 + p1 * p1;
    #pragma unroll
    for (int o = 16; o; o >>= 1) q += __shfl_xor_sync(0xFFFFFFFFu, q, o);
    if (lane == 0) nrm[row] = q;
}

// ---------------- per-launch init (deterministic across graph replays) ----------------
__global__ void init_kernel() {
    int idx = blockIdx.x * blockDim.x + threadIdx.x;
    if (idx < BATCH * NN) { g_u[idx] = 0.f; g_v[idx] = 0.f; g_a[idx] = 1.f; g_b[idx] = 1.f; }
    if (idx < MAX_ITER * BATCH) g_errA[idx] = 0.f;
    if (idx == 0) { g_cost = 0.0; g_bar_cnt = 0u; g_bar_gen = 0u; }
}

// ---------------- K = exp((2 x.y - |x|^2 - |y|^2)/eps), 64x64 tiles ----------------
__global__ void buildK_kernel() {
    __shared__ float As[64][65];
    __shared__ float Bs[64][65];
    __shared__ float x2s[64], y2s[64];
    int bx = blockIdx.x;
    int batch = bx >> 8;
    int tile  = bx & 255;
    int i0 = (tile >> 4) * 64, j0 = (tile & 15) * 64;
    int t = threadIdx.x;
    const float* xsrc = g_xs + (batch * NN + i0) * DD;
    const float* ysrc = g_ys + (batch * NN + j0) * DD;
    #pragma unroll
    for (int k = 0; k < 16; k++) {
        int lin = k * 256 + t;
        As[lin >> 6][lin & 63] = xsrc[lin];
        Bs[lin >> 6][lin & 63] = ysrc[lin];
    }
    if (t < 64) { x2s[t] = g_x2[batch * NN + i0 + t]; y2s[t] = g_y2[batch * NN + j0 + t]; }
    __syncthreads();
    int tx = t & 15, ty = t >> 4;
    float acc[4][4];
    #pragma unroll
    for (int a = 0; a < 4; a++)
        #pragma unroll
        for (int b = 0; b < 4; b++) acc[a][b] = 0.f;
    #pragma unroll
    for (int d = 0; d < 64; d++) {
        float av[4], bv[4];
        #pragma unroll
        for (int ii = 0; ii < 4; ii++) av[ii] = As[ty + ii * 16][d];
        #pragma unroll
        for (int jj = 0; jj < 4; jj++) bv[jj] = Bs[tx + jj * 16][d];
        #pragma unroll
        for (int ii = 0; ii < 4; ii++)
            #pragma unroll
            for (int jj = 0; jj < 4; jj++) acc[ii][jj] += av[ii] * bv[jj];
    }
    float* Kb = g_K + batch * NN * NN;
    #pragma unroll
    for (int ii = 0; ii < 4; ii++) {
        int i = i0 + ty + ii * 16;
        float xi2 = x2s[ty + ii * 16];
        #pragma unroll
        for (int jj = 0; jj < 4; jj++) {
            int j = j0 + tx + jj * 16;
            float m = (2.0f * acc[ii][jj] - xi2 - y2s[tx + jj * 16]) * INV_EPS;
            Kb[i * NN + j] = __expf(m);
        }
    }
}

// ---------------- persistent Sinkhorn loop + cost + finalize ----------------
// Block bk: batch = bk>>3, seg = bk&7.
// Row phase: rows seg*128..+128 of batch (u,a update).
// Col phase: cols seg*128..+128 of batch (v,b update).
__global__ void __launch_bounds__(TB, 1) sinkhorn_persistent(float* __restrict__ out) {
    int bk  = blockIdx.x;
    int tid = threadIdx.x;
    int batch = bk >> 3;
    int seg   = bk & 7;
    int w = tid >> 5, lane = tid & 31;

    __shared__ float4 vec4[256];        // b (row/cost phases) or a (col phase)
    __shared__ float  rsum[128];
    __shared__ float  psum[TB];
    __shared__ int    s_done;
    float* vecs = (float*)vec4;

    int it = 0;
    for (; it < MAX_ITER; ++it) {
        // ======== row phase: r_i = sum_j K_ij b_j ; update u, a ========
        if (tid < 256) vec4[tid] = ((const float4*)(g_b + batch * NN))[tid];
        __syncthreads();
        {
            int ibase = seg * 128 + w * 4;
            const float4* K0 = (const float4*)(g_K + (size_t)(batch * NN + ibase) * NN);
            float s0 = 0.f, s1 = 0.f, s2 = 0.f, s3 = 0.f;
            #pragma unroll
            for (int k = 0; k < 8; k++) {
                float4 bv = vec4[k * 32 + lane];
                float4 k0 = K0[          k * 32 + lane];
                float4 k1 = K0[256 +     k * 32 + lane];
                float4 k2 = K0[512 +     k * 32 + lane];
                float4 k3 = K0[768 +     k * 32 + lane];
                s0 += k0.x * bv.x + k0.y * bv.y + k0.z * bv.z + k0.w * bv.w;
                s1 += k1.x * bv.x + k1.y * bv.y + k1.z * bv.z + k1.w * bv.w;
                s2 += k2.x * bv.x + k2.y * bv.y + k2.z * bv.z + k2.w * bv.w;
                s3 += k3.x * bv.x + k3.y * bv.y + k3.z * bv.z + k3.w * bv.w;
            }
            #pragma unroll
            for (int o = 16; o; o >>= 1) {
                s0 += __shfl_xor_sync(0xFFFFFFFFu, s0, o);
                s1 += __shfl_xor_sync(0xFFFFFFFFu, s1, o);
                s2 += __shfl_xor_sync(0xFFFFFFFFu, s2, o);
                s3 += __shfl_xor_sync(0xFFFFFFFFu, s3, o);
            }
            if (lane == 0) {
                rsum[w * 4 + 0] = s0; rsum[w * 4 + 1] = s1;
                rsum[w * 4 + 2] = s2; rsum[w * 4 + 3] = s3;
            }
        }
        __syncthreads();
        if (tid < 128) {
            int gi = batch * NN + seg * 128 + tid;
            float uo = g_u[gi];
            float a  = g_a[gi];
            float lse = logf(fmaf(a, rsum[tid], 1e-6f));   // accurate log: iteration fidelity
            float un  = EPSF * (LOG_MU - lse) + uo;
            g_u[gi] = un;
            g_a[gi] = expf(un * INV_EPS);
            psum[tid] = fabsf(un - uo);
        }
        __syncthreads();
        if (tid == 0) {
            float d = 0.f;
            #pragma unroll
            for (int k = 0; k < 128; k++) d += psum[k];
            atomicAdd(&g_errA[it * BATCH + batch], d);
        }
        grid_barrier();   // new a visible everywhere; err slot complete

        // ======== col phase: s_j = sum_i K_ij a_i ; update v, b ========
        if (tid < 256) vec4[tid] = ((const float4*)(g_a + batch * NN))[tid];
        __syncthreads();
        {
            int tx = tid & 127, ig = tid >> 7;     // 8 i-groups of 128 rows
            int j = seg * 128 + tx;
            const float* Kc = g_K + (size_t)(batch * NN + ig * 128) * NN + j;
            const float* as = vecs + ig * 128;
            float s = 0.f;
            #pragma unroll 8
            for (int i = 0; i < 128; i++) s += Kc[(size_t)i * NN] * as[i];
            psum[tid] = s;
        }
        __syncthreads();
        if (tid < 128) {
            float s = psum[tid];
            #pragma unroll
            for (int k = 1; k < 8; k++) s += psum[tid + k * 128];
            int gj = batch * NN + seg * 128 + tid;
            float vo = g_v[gj], b = g_b[gj];
            float lse = logf(fmaf(b, s, 1e-6f));
            float vn  = EPSF * (LOG_MU - lse) + vo;
            g_v[gj] = vn;
            g_b[gj] = expf(vn * INV_EPS);
        }
        grid_barrier();   // new b visible; safe to read err and proceed

        // ======== convergence check (identical on every block) ========
        if (tid == 0) {
            float e = 0.f;
            #pragma unroll
            for (int bb = 0; bb < BATCH; bb++) e += g_errA[it * BATCH + bb];
            s_done = (e * (1.0f / BATCH) < THRESH) ? 1 : 0;
        }
        __syncthreads();
        if (s_done) break;
    }

    // ======== cost phase: -eps * sum_ij a_i b_j K_ij ln K_ij ========
    if (tid < 256) vec4[tid] = ((const float4*)(g_b + batch * NN))[tid];
    __syncthreads();
    {
        int ibase = seg * 128 + w * 4;
        const float4* K0 = (const float4*)(g_K + (size_t)(batch * NN + ibase) * NN);
        float s0 = 0.f, s1 = 0.f, s2 = 0.f, s3 = 0.f;
        #pragma unroll
        for (int k = 0; k < 8; k++) {
            float4 bv = vec4[k * 32 + lane];
            float4 k0 = K0[          k * 32 + lane];
            float4 k1 = K0[256 +     k * 32 + lane];
            float4 k2 = K0[512 +     k * 32 + lane];
            float4 k3 = K0[768 +     k * 32 + lane];
            s0 += k0.x * bv.x * __logf(k0.x) + k0.y * bv.y * __logf(k0.y)
                + k0.z * bv.z * __logf(k0.z) + k0.w * bv.w * __logf(k0.w);
            s1 += k1.x * bv.x * __logf(k1.x) + k1.y * bv.y * __logf(k1.y)
                + k1.z * bv.z * __logf(k1.z) + k1.w * bv.w * __logf(k1.w);
            s2 += k2.x * bv.x * __logf(k2.x) + k2.y * bv.y * __logf(k2.y)
                + k2.z * bv.z * __logf(k2.z) + k2.w * bv.w * __logf(k2.w);
            s3 += k3.x * bv.x * __logf(k3.x) + k3.y * bv.y * __logf(k3.y)
                + k3.z * bv.z * __logf(k3.z) + k3.w * bv.w * __logf(k3.w);
        }
        #pragma unroll
        for (int o = 16; o; o >>= 1) {
            s0 += __shfl_xor_sync(0xFFFFFFFFu, s0, o);
            s1 += __shfl_xor_sync(0xFFFFFFFFu, s1, o);
            s2 += __shfl_xor_sync(0xFFFFFFFFu, s2, o);
            s3 += __shfl_xor_sync(0xFFFFFFFFu, s3, o);
        }
        if (lane == 0) {
            rsum[w * 4 + 0] = s0; rsum[w * 4 + 1] = s1;
            rsum[w * 4 + 2] = s2; rsum[w * 4 + 3] = s3;
        }
    }
    __syncthreads();
    if (tid < 128) {
        int gi = batch * NN + seg * 128 + tid;
        psum[tid] = g_a[gi] * rsum[tid];
    }
    __syncthreads();
    if (tid == 0) {
        float bsum = 0.f;
        #pragma unroll
        for (int k = 0; k < 128; k++) bsum += psum[k];
        atomicAdd(&g_cost, (double)(-EPSF * bsum));
    }
    grid_barrier();
    if (bk == 0 && tid == 0) out[0] = (float)(g_cost * (1.0 / (double)BATCH));
}

// ---------------- launch ----------------
extern "C" void kernel_launch(void* const* d_in, const int* in_sizes, int n_in,
                              void* d_out, int out_size) {
    const float* x = (const float*)d_in[0];
    const float* y = (const float*)d_in[1];
    float* out = (float*)d_out;
    (void)in_sizes; (void)n_in; (void)out_size;

    softmax_kernel<<<4096, 256>>>(x, y);   // 32768 rows, warp per row
    init_kernel<<<64, 256>>>();
    buildK_kernel<<<4096, 256>>>();        // 16 batches x 256 tiles of 64x64
    sinkhorn_persistent<<<GB, TB>>>(out);  // whole Sinkhorn loop + cost + finalize
}

// round 4
// speedup vs baseline: 5.5016x; 1.4860x over previous
#include <cuda_runtime.h>

#define BATCH 16
#define NN    1024
#define DD    64
#define EPSF      0.1f
#define INV_EPS   10.0f
#define LOG_MU   (-6.9314616f)   // log(1/1024 + 1e-8)
#define THRESH    0.1f
#define MAX_ITER  100
#define GB        128            // persistent grid: 128 blocks (<= 148 SMs, all co-resident)
#define TB        1024

// ---------------- device scratch (static: no allocations allowed) ----------------
__device__ float g_K [BATCH * NN * NN];   // 64 MB: K = exp(-C/eps), L2-resident
__device__ float g_xs[BATCH * NN * DD];
__device__ float g_ys[BATCH * NN * DD];
__device__ float g_x2[BATCH * NN];
__device__ float g_y2[BATCH * NN];
__device__ float g_u [BATCH * NN];
__device__ float g_v [BATCH * NN];
__device__ float g_a [BATCH * NN];        // exp(u/eps)
__device__ float g_b [BATCH * NN];        // exp(v/eps)
__device__ float g_errA[MAX_ITER * BATCH];// per-iteration err slots (no reset races)
__device__ double   g_cost;
__device__ unsigned g_bar_cnt;
__device__ unsigned g_bar_gen;

// ---------------- software grid barrier (all GB blocks co-resident) ----------------
__device__ __forceinline__ void grid_barrier() {
    __threadfence();
    __syncthreads();
    if (threadIdx.x == 0) {
        unsigned gen = *((volatile unsigned*)&g_bar_gen);
        if (atomicAdd(&g_bar_cnt, 1u) == GB - 1u) {
            g_bar_cnt = 0u;
            __threadfence();
            *((volatile unsigned*)&g_bar_gen) = gen + 1u;
        } else {
            while (*((volatile unsigned*)&g_bar_gen) == gen) { __nanosleep(64); }
        }
    }
    __syncthreads();
}

__device__ __forceinline__ float to_tf32(float x) {
    asm("cvt.rna.tf32.f32 %0, %0;" : "+f"(x));
    return x;
}

// ---------------- softmax over last dim (D=64), one warp per row ----------------
__global__ void softmax_kernel(const float* __restrict__ x, const float* __restrict__ y) {
    int gwarp = (blockIdx.x * blockDim.x + threadIdx.x) >> 5;
    int lane  = threadIdx.x & 31;
    const float* src; float* dst; float* nrm; int row;
    if (gwarp < BATCH * NN) { src = x; dst = g_xs; nrm = g_x2; row = gwarp; }
    else                    { src = y; dst = g_ys; nrm = g_y2; row = gwarp - BATCH * NN; }
    const float* r = src + row * DD;
    float e0 = r[lane], e1 = r[lane + 32];
    float m = fmaxf(e0, e1);
    #pragma unroll
    for (int o = 16; o; o >>= 1) m = fmaxf(m, __shfl_xor_sync(0xFFFFFFFFu, m, o));
    float s0 = __expf(e0 - m), s1 = __expf(e1 - m);
    float s = s0 + s1;
    #pragma unroll
    for (int o = 16; o; o >>= 1) s += __shfl_xor_sync(0xFFFFFFFFu, s, o);
    float inv = 1.0f / s;
    float p0 = s0 * inv, p1 = s1 * inv;
    float* d = dst + row * DD;
    d[lane] = p0; d[lane + 32] = p1;
    float q = p0 * p0 + p1 * p1;
    #pragma unroll
    for (int o = 16; o; o >>= 1) q += __shfl_xor_sync(0xFFFFFFFFu, q, o);
    if (lane == 0) nrm[row] = q;
}

// ---------------- per-launch init (deterministic across graph replays) ----------------
__global__ void init_kernel() {
    int idx = blockIdx.x * blockDim.x + threadIdx.x;
    if (idx < BATCH * NN) { g_u[idx] = 0.f; g_v[idx] = 0.f; g_a[idx] = 1.f; g_b[idx] = 1.f; }
    if (idx < MAX_ITER * BATCH) g_errA[idx] = 0.f;
    if (idx == 0) { g_cost = 0.0; g_bar_cnt = 0u; g_bar_gen = 0u; }
}

// ---------------- K = exp((2 x.y - |x|^2 - |y|^2)/eps) via tf32 tensor-core MMA ----------------
// Block: 64(i) x 64(j) tile, 256 threads = 8 warps (4 m-rows x 2 n-cols), warp tile 16x32.
// mma.sync.m16n8k8.row.col.f32.tf32.tf32.f32, fp32 accumulate.
#define XS_STRIDE 68   // (row*68+col)%32 = (row*4+col)%32 -> conflict-free fragment LDS
__global__ void __launch_bounds__(256) buildK_mma() {
    __shared__ float xs[64 * XS_STRIDE];
    __shared__ float ys[64 * XS_STRIDE];
    __shared__ float x2s[64], y2s[64];

    int bx = blockIdx.x;
    int batch = bx >> 8;          // 256 tiles per batch (16 i-tiles x 16 j-tiles)
    int tile  = bx & 255;
    int i0 = (tile >> 4) * 64, j0 = (tile & 15) * 64;
    int t = threadIdx.x;

    // Load tiles to shared, converting to tf32 (round-to-nearest) once.
    const float4* xsrc = (const float4*)(g_xs + (size_t)(batch * NN + i0) * DD);
    const float4* ysrc = (const float4*)(g_ys + (size_t)(batch * NN + j0) * DD);
    #pragma unroll
    for (int k = 0; k < 4; k++) {
        int lin = k * 256 + t;                 // float4 index: row = lin>>4, col4 = lin&15
        int row = lin >> 4, c = (lin & 15) * 4;
        float4 vx = xsrc[lin];
        float4 vy = ysrc[lin];
        vx.x = to_tf32(vx.x); vx.y = to_tf32(vx.y); vx.z = to_tf32(vx.z); vx.w = to_tf32(vx.w);
        vy.x = to_tf32(vy.x); vy.y = to_tf32(vy.y); vy.z = to_tf32(vy.z); vy.w = to_tf32(vy.w);
        *((float4*)(xs + row * XS_STRIDE + c)) = vx;
        *((float4*)(ys + row * XS_STRIDE + c)) = vy;
    }
    if (t < 64)            x2s[t]      = g_x2[batch * NN + i0 + t];
    else if (t < 128)      y2s[t - 64] = g_y2[batch * NN + j0 + (t - 64)];
    __syncthreads();

    int w = t >> 5, lane = t & 31;
    int mo = (w >> 1) * 16;       // warp m-offset within 64
    int no = (w & 1) * 32;        // warp n-offset within 64
    int gr = lane >> 2, gc = lane & 3;

    float acc[4][4];              // 4 n-tiles of m16n8, 4 f32 each
    #pragma unroll
    for (int nt = 0; nt < 4; nt++)
        #pragma unroll
        for (int q = 0; q < 4; q++) acc[nt][q] = 0.f;

    #pragma unroll
    for (int k0 = 0; k0 < 64; k0 += 8) {
        unsigned a0, a1, a2, a3;
        {
            const float* base = xs + (mo + gr) * XS_STRIDE + k0 + gc;
            a0 = __float_as_uint(base[0]);
            a1 = __float_as_uint(base[8 * XS_STRIDE]);
            a2 = __float_as_uint(base[4]);
            a3 = __float_as_uint(base[8 * XS_STRIDE + 4]);
        }
        #pragma unroll
        for (int nt = 0; nt < 4; nt++) {
            const float* bb = ys + (no + nt * 8 + gr) * XS_STRIDE + k0 + gc;
            unsigned b0 = __float_as_uint(bb[0]);
            unsigned b1 = __float_as_uint(bb[4]);
            asm volatile(
                "mma.sync.aligned.m16n8k8.row.col.f32.tf32.tf32.f32 "
                "{%0,%1,%2,%3}, {%4,%5,%6,%7}, {%8,%9}, {%0,%1,%2,%3};"
                : "+f"(acc[nt][0]), "+f"(acc[nt][1]), "+f"(acc[nt][2]), "+f"(acc[nt][3])
                : "r"(a0), "r"(a1), "r"(a2), "r"(a3), "r"(b0), "r"(b1));
        }
    }

    // Epilogue: m = (2*dot - x2_i - y2_j)/eps ; K = exp(m). float2 stores.
    float* Kb = g_K + (size_t)batch * NN * NN;
    float xi0 = x2s[mo + gr], xi1 = x2s[mo + gr + 8];
    int r0 = i0 + mo + gr, r1 = r0 + 8;
    #pragma unroll
    for (int nt = 0; nt < 4; nt++) {
        int jc = j0 + no + nt * 8 + gc * 2;
        float yj0 = y2s[no + nt * 8 + gc * 2];
        float yj1 = y2s[no + nt * 8 + gc * 2 + 1];
        float2 o0, o1;
        o0.x = __expf((2.0f * acc[nt][0] - xi0 - yj0) * INV_EPS);
        o0.y = __expf((2.0f * acc[nt][1] - xi0 - yj1) * INV_EPS);
        o1.x = __expf((2.0f * acc[nt][2] - xi1 - yj0) * INV_EPS);
        o1.y = __expf((2.0f * acc[nt][3] - xi1 - yj1) * INV_EPS);
        *((float2*)(Kb + (size_t)r0 * NN + jc)) = o0;
        *((float2*)(Kb + (size_t)r1 * NN + jc)) = o1;
    }
}

// ---------------- persistent Sinkhorn loop + cost + finalize ----------------
// Block bk: batch = bk>>3, seg = bk&7.
__global__ void __launch_bounds__(TB, 1) sinkhorn_persistent(float* __restrict__ out) {
    int bk  = blockIdx.x;
    int tid = threadIdx.x;
    int batch = bk >> 3;
    int seg   = bk & 7;
    int w = tid >> 5, lane = tid & 31;

    __shared__ float4 vec4[256];        // b (row/cost phases) or a (col phase)
    __shared__ float  rsum[128];
    __shared__ float  psum[TB];
    __shared__ int    s_done;
    float* vecs = (float*)vec4;

    int it = 0;
    for (; it < MAX_ITER; ++it) {
        // ======== row phase: r_i = sum_j K_ij b_j ; update u, a ========
        if (tid < 256) vec4[tid] = ((const float4*)(g_b + batch * NN))[tid];
        __syncthreads();
        {
            int ibase = seg * 128 + w * 4;
            const float4* K0 = (const float4*)(g_K + (size_t)(batch * NN + ibase) * NN);
            float s0 = 0.f, s1 = 0.f, s2 = 0.f, s3 = 0.f;
            #pragma unroll
            for (int k = 0; k < 8; k++) {
                float4 bv = vec4[k * 32 + lane];
                float4 k0 = K0[          k * 32 + lane];
                float4 k1 = K0[256 +     k * 32 + lane];
                float4 k2 = K0[512 +     k * 32 + lane];
                float4 k3 = K0[768 +     k * 32 + lane];
                s0 += k0.x * bv.x + k0.y * bv.y + k0.z * bv.z + k0.w * bv.w;
                s1 += k1.x * bv.x + k1.y * bv.y + k1.z * bv.z + k1.w * bv.w;
                s2 += k2.x * bv.x + k2.y * bv.y + k2.z * bv.z + k2.w * bv.w;
                s3 += k3.x * bv.x + k3.y * bv.y + k3.z * bv.z + k3.w * bv.w;
            }
            #pragma unroll
            for (int o = 16; o; o >>= 1) {
                s0 += __shfl_xor_sync(0xFFFFFFFFu, s0, o);
                s1 += __shfl_xor_sync(0xFFFFFFFFu, s1, o);
                s2 += __shfl_xor_sync(0xFFFFFFFFu, s2, o);
                s3 += __shfl_xor_sync(0xFFFFFFFFu, s3, o);
            }
            if (lane == 0) {
                rsum[w * 4 + 0] = s0; rsum[w * 4 + 1] = s1;
                rsum[w * 4 + 2] = s2; rsum[w * 4 + 3] = s3;
            }
        }
        __syncthreads();
        if (tid < 128) {
            int gi = batch * NN + seg * 128 + tid;
            float uo = g_u[gi];
            float a  = g_a[gi];
            float lse = logf(fmaf(a, rsum[tid], 1e-6f));   // accurate log: iteration fidelity
            float un  = EPSF * (LOG_MU - lse) + uo;
            g_u[gi] = un;
            g_a[gi] = expf(un * INV_EPS);
            psum[tid] = fabsf(un - uo);
        }
        __syncthreads();
        if (tid == 0) {
            float d = 0.f;
            #pragma unroll
            for (int k = 0; k < 128; k++) d += psum[k];
            atomicAdd(&g_errA[it * BATCH + batch], d);
        }
        grid_barrier();   // new a visible everywhere; err slot complete

        // ======== col phase: s_j = sum_i K_ij a_i ; update v, b ========
        if (tid < 256) vec4[tid] = ((const float4*)(g_a + batch * NN))[tid];
        __syncthreads();
        {
            int tx = tid & 127, ig = tid >> 7;     // 8 i-groups of 128 rows
            int j = seg * 128 + tx;
            const float* Kc = g_K + (size_t)(batch * NN + ig * 128) * NN + j;
            const float* as = vecs + ig * 128;
            float s = 0.f;
            #pragma unroll 8
            for (int i = 0; i < 128; i++) s += Kc[(size_t)i * NN] * as[i];
            psum[tid] = s;
        }
        __syncthreads();
        if (tid < 128) {
            float s = psum[tid];
            #pragma unroll
            for (int k = 1; k < 8; k++) s += psum[tid + k * 128];
            int gj = batch * NN + seg * 128 + tid;
            float vo = g_v[gj], b = g_b[gj];
            float lse = logf(fmaf(b, s, 1e-6f));
            float vn  = EPSF * (LOG_MU - lse) + vo;
            g_v[gj] = vn;
            g_b[gj] = expf(vn * INV_EPS);
        }
        grid_barrier();   // new b visible; safe to read err and proceed

        // ======== convergence check (identical on every block) ========
        if (tid == 0) {
            float e = 0.f;
            #pragma unroll
            for (int bb = 0; bb < BATCH; bb++) e += g_errA[it * BATCH + bb];
            s_done = (e * (1.0f / BATCH) < THRESH) ? 1 : 0;
        }
        __syncthreads();
        if (s_done) break;
    }

    // ======== cost phase: -eps * sum_ij a_i b_j K_ij ln K_ij ========
    if (tid < 256) vec4[tid] = ((const float4*)(g_b + batch * NN))[tid];
    __syncthreads();
    {
        int ibase = seg * 128 + w * 4;
        const float4* K0 = (const float4*)(g_K + (size_t)(batch * NN + ibase) * NN);
        float s0 = 0.f, s1 = 0.f, s2 = 0.f, s3 = 0.f;
        #pragma unroll
        for (int k = 0; k < 8; k++) {
            float4 bv = vec4[k * 32 + lane];
            float4 k0 = K0[          k * 32 + lane];
            float4 k1 = K0[256 +     k * 32 + lane];
            float4 k2 = K0[512 +     k * 32 + lane];
            float4 k3 = K0[768 +     k * 32 + lane];
            s0 += k0.x * bv.x * __logf(k0.x) + k0.y * bv.y * __logf(k0.y)
                + k0.z * bv.z * __logf(k0.z) + k0.w * bv.w * __logf(k0.w);
            s1 += k1.x * bv.x * __logf(k1.x) + k1.y * bv.y * __logf(k1.y)
                + k1.z * bv.z * __logf(k1.z) + k1.w * bv.w * __logf(k1.w);
            s2 += k2.x * bv.x * __logf(k2.x) + k2.y * bv.y * __logf(k2.y)
                + k2.z * bv.z * __logf(k2.z) + k2.w * bv.w * __logf(k2.w);
            s3 += k3.x * bv.x * __logf(k3.x) + k3.y * bv.y * __logf(k3.y)
                + k3.z * bv.z * __logf(k3.z) + k3.w * bv.w * __logf(k3.w);
        }
        #pragma unroll
        for (int o = 16; o; o >>= 1) {
            s0 += __shfl_xor_sync(0xFFFFFFFFu, s0, o);
            s1 += __shfl_xor_sync(0xFFFFFFFFu, s1, o);
            s2 += __shfl_xor_sync(0xFFFFFFFFu, s2, o);
            s3 += __shfl_xor_sync(0xFFFFFFFFu, s3, o);
        }
        if (lane == 0) {
            rsum[w * 4 + 0] = s0; rsum[w * 4 + 1] = s1;
            rsum[w * 4 + 2] = s2; rsum[w * 4 + 3] = s3;
        }
    }
    __syncthreads();
    if (tid < 128) {
        int gi = batch * NN + seg * 128 + tid;
        psum[tid] = g_a[gi] * rsum[tid];
    }
    __syncthreads();
    if (tid == 0) {
        float bsum = 0.f;
        #pragma unroll
        for (int k = 0; k < 128; k++) bsum += psum[k];
        atomicAdd(&g_cost, (double)(-EPSF * bsum));
    }
    grid_barrier();
    if (bk == 0 && tid == 0) out[0] = (float)(g_cost * (1.0 / (double)BATCH));
}

// ---------------- launch ----------------
extern "C" void kernel_launch(void* const* d_in, const int* in_sizes, int n_in,
                              void* d_out, int out_size) {
    const float* x = (const float*)d_in[0];
    const float* y = (const float*)d_in[1];
    float* out = (float*)d_out;
    (void)in_sizes; (void)n_in; (void)out_size;

    softmax_kernel<<<4096, 256>>>(x, y);   // 32768 rows, warp per row
    init_kernel<<<64, 256>>>();
    buildK_mma<<<4096, 256>>>();           // 16 batches x 256 tiles of 64x64, tf32 HMMA
    sinkhorn_persistent<<<GB, TB>>>(out);  // whole Sinkhorn loop + cost + finalize
}

// round 5
// speedup vs baseline: 6.0986x; 1.1085x over previous
#include <cuda_runtime.h>
#include <cuda_bf16.h>

#define BATCH 16
#define NN    1024
#define DD    64
#define EPSF      0.1f
#define INV_EPS   10.0f
#define LOG_MU   (-6.9314616f)   // log(1/1024 + 1e-8)
#define THRESH    0.1f
#define MAX_ITER  100
#define GB        128            // persistent grid: 128 blocks, all co-resident
#define TB        1024

// ---------------- device scratch (static: no allocations allowed) ----------------
__device__ __nv_bfloat16 g_Kh[BATCH * NN * NN];  // 32 MB: K = exp(-C/eps), bf16, L2-resident
__device__ float g_xs[BATCH * NN * DD];
__device__ float g_ys[BATCH * NN * DD];
__device__ float g_x2[BATCH * NN];
__device__ float g_y2[BATCH * NN];
__device__ float g_u [BATCH * NN];
__device__ float g_v [BATCH * NN];
__device__ float g_a [BATCH * NN];        // exp(u/eps)
__device__ float g_b [BATCH * NN];        // exp(v/eps)
__device__ float g_errA[MAX_ITER * BATCH];// per-iteration err slots (no reset races)
__device__ double   g_cost;
__device__ unsigned g_bar_cnt;
__device__ unsigned g_bar_gen;

// ---------------- software grid barrier (all GB blocks co-resident) ----------------
__device__ __forceinline__ void grid_barrier() {
    __threadfence();
    __syncthreads();
    if (threadIdx.x == 0) {
        unsigned gen = *((volatile unsigned*)&g_bar_gen);
        if (atomicAdd(&g_bar_cnt, 1u) == GB - 1u) {
            g_bar_cnt = 0u;
            __threadfence();
            *((volatile unsigned*)&g_bar_gen) = gen + 1u;
        } else {
            while (*((volatile unsigned*)&g_bar_gen) == gen) { __nanosleep(64); }
        }
    }
    __syncthreads();
}

__device__ __forceinline__ float to_tf32(float x) {
    asm("cvt.rna.tf32.f32 %0, %0;" : "+f"(x));
    return x;
}

// dot of 8 bf16 (one uint4) with 8 floats (two float4)
__device__ __forceinline__ float dot8(uint4 q, float4 b0, float4 b1) {
    float2 p0 = __bfloat1622float2(*(const __nv_bfloat162*)&q.x);
    float2 p1 = __bfloat1622float2(*(const __nv_bfloat162*)&q.y);
    float2 p2 = __bfloat1622float2(*(const __nv_bfloat162*)&q.z);
    float2 p3 = __bfloat1622float2(*(const __nv_bfloat162*)&q.w);
    return p0.x*b0.x + p0.y*b0.y + p1.x*b0.z + p1.y*b0.w
         + p2.x*b1.x + p2.y*b1.y + p3.x*b1.z + p3.y*b1.w;
}

// sum of k*b*ln(k) over 8 bf16 k's
__device__ __forceinline__ float dot8log(uint4 q, float4 b0, float4 b1) {
    float2 p0 = __bfloat1622float2(*(const __nv_bfloat162*)&q.x);
    float2 p1 = __bfloat1622float2(*(const __nv_bfloat162*)&q.y);
    float2 p2 = __bfloat1622float2(*(const __nv_bfloat162*)&q.z);
    float2 p3 = __bfloat1622float2(*(const __nv_bfloat162*)&q.w);
    return p0.x*b0.x*__logf(p0.x) + p0.y*b0.y*__logf(p0.y)
         + p1.x*b0.z*__logf(p1.x) + p1.y*b0.w*__logf(p1.y)
         + p2.x*b1.x*__logf(p2.x) + p2.y*b1.y*__logf(p2.y)
         + p3.x*b1.z*__logf(p3.x) + p3.y*b1.w*__logf(p3.y);
}

// ---------------- softmax over last dim (D=64) + fused per-launch init ----------------
__global__ void softmax_kernel(const float* __restrict__ x, const float* __restrict__ y) {
    int gidx = blockIdx.x * blockDim.x + threadIdx.x;
    if (gidx < BATCH * NN) { g_u[gidx] = 0.f; g_v[gidx] = 0.f; g_a[gidx] = 1.f; g_b[gidx] = 1.f; }
    if (gidx < MAX_ITER * BATCH) g_errA[gidx] = 0.f;
    if (gidx == 0) { g_cost = 0.0; g_bar_cnt = 0u; g_bar_gen = 0u; }

    int gwarp = gidx >> 5;
    int lane  = threadIdx.x & 31;
    const float* src; float* dst; float* nrm; int row;
    if (gwarp < BATCH * NN) { src = x; dst = g_xs; nrm = g_x2; row = gwarp; }
    else                    { src = y; dst = g_ys; nrm = g_y2; row = gwarp - BATCH * NN; }
    const float* r = src + row * DD;
    float e0 = r[lane], e1 = r[lane + 32];
    float m = fmaxf(e0, e1);
    #pragma unroll
    for (int o = 16; o; o >>= 1) m = fmaxf(m, __shfl_xor_sync(0xFFFFFFFFu, m, o));
    float s0 = __expf(e0 - m), s1 = __expf(e1 - m);
    float s = s0 + s1;
    #pragma unroll
    for (int o = 16; o; o >>= 1) s += __shfl_xor_sync(0xFFFFFFFFu, s, o);
    float inv = 1.0f / s;
    float p0 = s0 * inv, p1 = s1 * inv;
    float* d = dst + row * DD;
    d[lane] = p0; d[lane + 32] = p1;
    float q = p0 * p0 + p1 * p1;
    #pragma unroll
    for (int o = 16; o; o >>= 1) q += __shfl_xor_sync(0xFFFFFFFFu, q, o);
    if (lane == 0) nrm[row] = q;
}

// ---------------- K = exp((2 x.y - |x|^2 - |y|^2)/eps) via tf32 MMA, bf16 store ----------------
#define XS_STRIDE 68   // (row*68+col)%32 = (row*4+col)%32 -> conflict-free fragment LDS
__global__ void __launch_bounds__(256) buildK_mma() {
    __shared__ float xs[64 * XS_STRIDE];
    __shared__ float ys[64 * XS_STRIDE];
    __shared__ float x2s[64], y2s[64];

    int bx = blockIdx.x;
    int batch = bx >> 8;          // 256 tiles per batch (16 i-tiles x 16 j-tiles)
    int tile  = bx & 255;
    int i0 = (tile >> 4) * 64, j0 = (tile & 15) * 64;
    int t = threadIdx.x;

    const float4* xsrc = (const float4*)(g_xs + (size_t)(batch * NN + i0) * DD);
    const float4* ysrc = (const float4*)(g_ys + (size_t)(batch * NN + j0) * DD);
    #pragma unroll
    for (int k = 0; k < 4; k++) {
        int lin = k * 256 + t;
        int row = lin >> 4, c = (lin & 15) * 4;
        float4 vx = xsrc[lin];
        float4 vy = ysrc[lin];
        vx.x = to_tf32(vx.x); vx.y = to_tf32(vx.y); vx.z = to_tf32(vx.z); vx.w = to_tf32(vx.w);
        vy.x = to_tf32(vy.x); vy.y = to_tf32(vy.y); vy.z = to_tf32(vy.z); vy.w = to_tf32(vy.w);
        *((float4*)(xs + row * XS_STRIDE + c)) = vx;
        *((float4*)(ys + row * XS_STRIDE + c)) = vy;
    }
    if (t < 64)            x2s[t]      = g_x2[batch * NN + i0 + t];
    else if (t < 128)      y2s[t - 64] = g_y2[batch * NN + j0 + (t - 64)];
    __syncthreads();

    int w = t >> 5, lane = t & 31;
    int mo = (w >> 1) * 16;
    int no = (w & 1) * 32;
    int gr = lane >> 2, gc = lane & 3;

    float acc[4][4];
    #pragma unroll
    for (int nt = 0; nt < 4; nt++)
        #pragma unroll
        for (int q = 0; q < 4; q++) acc[nt][q] = 0.f;

    #pragma unroll
    for (int k0 = 0; k0 < 64; k0 += 8) {
        unsigned a0, a1, a2, a3;
        {
            const float* base = xs + (mo + gr) * XS_STRIDE + k0 + gc;
            a0 = __float_as_uint(base[0]);
            a1 = __float_as_uint(base[8 * XS_STRIDE]);
            a2 = __float_as_uint(base[4]);
            a3 = __float_as_uint(base[8 * XS_STRIDE + 4]);
        }
        #pragma unroll
        for (int nt = 0; nt < 4; nt++) {
            const float* bb = ys + (no + nt * 8 + gr) * XS_STRIDE + k0 + gc;
            unsigned b0 = __float_as_uint(bb[0]);
            unsigned b1 = __float_as_uint(bb[4]);
            asm volatile(
                "mma.sync.aligned.m16n8k8.row.col.f32.tf32.tf32.f32 "
                "{%0,%1,%2,%3}, {%4,%5,%6,%7}, {%8,%9}, {%0,%1,%2,%3};"
                : "+f"(acc[nt][0]), "+f"(acc[nt][1]), "+f"(acc[nt][2]), "+f"(acc[nt][3])
                : "r"(a0), "r"(a1), "r"(a2), "r"(a3), "r"(b0), "r"(b1));
        }
    }

    // Epilogue: K = exp((2*dot - x2_i - y2_j)/eps), store bf16x2
    __nv_bfloat16* Kb = g_Kh + (size_t)batch * NN * NN;
    float xi0 = x2s[mo + gr], xi1 = x2s[mo + gr + 8];
    int r0 = i0 + mo + gr, r1 = r0 + 8;
    #pragma unroll
    for (int nt = 0; nt < 4; nt++) {
        int jc = j0 + no + nt * 8 + gc * 2;
        float yj0 = y2s[no + nt * 8 + gc * 2];
        float yj1 = y2s[no + nt * 8 + gc * 2 + 1];
        float k00 = __expf((2.0f * acc[nt][0] - xi0 - yj0) * INV_EPS);
        float k01 = __expf((2.0f * acc[nt][1] - xi0 - yj1) * INV_EPS);
        float k10 = __expf((2.0f * acc[nt][2] - xi1 - yj0) * INV_EPS);
        float k11 = __expf((2.0f * acc[nt][3] - xi1 - yj1) * INV_EPS);
        *(__nv_bfloat162*)(Kb + (size_t)r0 * NN + jc) = __floats2bfloat162_rn(k00, k01);
        *(__nv_bfloat162*)(Kb + (size_t)r1 * NN + jc) = __floats2bfloat162_rn(k10, k11);
    }
}

// ---------------- persistent Sinkhorn loop + cost + finalize (bf16 K) ----------------
// Block bk: batch = bk>>3, seg = bk&7.
__global__ void __launch_bounds__(TB, 1) sinkhorn_persistent(float* __restrict__ out) {
    int bk  = blockIdx.x;
    int tid = threadIdx.x;
    int batch = bk >> 3;
    int seg   = bk & 7;
    int w = tid >> 5, lane = tid & 31;

    __shared__ float4 vec4[256];        // b (row/cost phases) or a (col phase), fp32
    __shared__ float  rsum[128];
    __shared__ float2 psum2[TB];
    __shared__ int    s_done;
    float* vecs = (float*)vec4;
    float* psum = (float*)psum2;

    int it = 0;
    for (; it < MAX_ITER; ++it) {
        // ======== row phase: r_i = sum_j K_ij b_j ; update u, a ========
        if (tid < 256) vec4[tid] = ((const float4*)(g_b + batch * NN))[tid];
        __syncthreads();
        {
            int ibase = seg * 128 + w * 4;      // 4 consecutive rows per warp
            const uint4* K0 = (const uint4*)(g_Kh + (size_t)(batch * NN + ibase) * NN);
            float s0 = 0.f, s1 = 0.f, s2 = 0.f, s3 = 0.f;
            #pragma unroll
            for (int k = 0; k < 4; k++) {
                int idx = k * 32 + lane;        // uint4 index within row (8 bf16 each)
                float4 b0 = vec4[idx * 2], b1 = vec4[idx * 2 + 1];
                s0 += dot8(K0[          idx], b0, b1);
                s1 += dot8(K0[128 +     idx], b0, b1);
                s2 += dot8(K0[256 +     idx], b0, b1);
                s3 += dot8(K0[384 +     idx], b0, b1);
            }
            #pragma unroll
            for (int o = 16; o; o >>= 1) {
                s0 += __shfl_xor_sync(0xFFFFFFFFu, s0, o);
                s1 += __shfl_xor_sync(0xFFFFFFFFu, s1, o);
                s2 += __shfl_xor_sync(0xFFFFFFFFu, s2, o);
                s3 += __shfl_xor_sync(0xFFFFFFFFu, s3, o);
            }
            if (lane == 0) {
                rsum[w * 4 + 0] = s0; rsum[w * 4 + 1] = s1;
                rsum[w * 4 + 2] = s2; rsum[w * 4 + 3] = s3;
            }
        }
        __syncthreads();
        if (tid < 128) {
            int gi = batch * NN + seg * 128 + tid;
            float uo = g_u[gi];
            float a  = g_a[gi];
            float lse = logf(fmaf(a, rsum[tid], 1e-6f));   // accurate log: iteration fidelity
            float un  = EPSF * (LOG_MU - lse) + uo;
            g_u[gi] = un;
            g_a[gi] = expf(un * INV_EPS);
            psum[tid] = fabsf(un - uo);
        }
        __syncthreads();
        if (tid == 0) {
            float d = 0.f;
            #pragma unroll
            for (int k = 0; k < 128; k++) d += psum[k];
            atomicAdd(&g_errA[it * BATCH + batch], d);
        }
        grid_barrier();   // new a visible everywhere; err slot complete

        // ======== col phase: s_j = sum_i K_ij a_i ; update v, b ========
        if (tid < 256) vec4[tid] = ((const float4*)(g_a + batch * NN))[tid];
        __syncthreads();
        {
            int tx = tid & 63, ig = tid >> 6;   // 16 i-groups of 64 rows, 64 col-pairs
            const __nv_bfloat162* Kc =
                (const __nv_bfloat162*)(g_Kh + (size_t)(batch * NN + ig * 64) * NN)
                + seg * 64 + tx;
            const float* as = vecs + ig * 64;
            float sx = 0.f, sy = 0.f;
            #pragma unroll 8
            for (int i = 0; i < 64; i++) {
                float2 kv = __bfloat1622float2(Kc[(size_t)i * (NN / 2)]);
                float av = as[i];
                sx += kv.x * av; sy += kv.y * av;
            }
            psum2[tid] = make_float2(sx, sy);
        }
        __syncthreads();
        if (tid < 64) {
            float2 s = psum2[tid];
            #pragma unroll
            for (int k = 1; k < 16; k++) {
                float2 p = psum2[k * 64 + tid];
                s.x += p.x; s.y += p.y;
            }
            int gj = batch * NN + seg * 128 + tid * 2;
            float vo0 = g_v[gj], b0 = g_b[gj];
            float vo1 = g_v[gj + 1], b1 = g_b[gj + 1];
            float vn0 = EPSF * (LOG_MU - logf(fmaf(b0, s.x, 1e-6f))) + vo0;
            float vn1 = EPSF * (LOG_MU - logf(fmaf(b1, s.y, 1e-6f))) + vo1;
            g_v[gj]     = vn0;  g_b[gj]     = expf(vn0 * INV_EPS);
            g_v[gj + 1] = vn1;  g_b[gj + 1] = expf(vn1 * INV_EPS);
        }
        grid_barrier();   // new b visible; safe to read err and proceed

        // ======== convergence check (identical on every block) ========
        if (tid == 0) {
            float e = 0.f;
            #pragma unroll
            for (int bb = 0; bb < BATCH; bb++) e += g_errA[it * BATCH + bb];
            s_done = (e * (1.0f / BATCH) < THRESH) ? 1 : 0;
        }
        __syncthreads();
        if (s_done) break;
    }

    // ======== cost phase: -eps * sum_ij a_i b_j K_ij ln K_ij ========
    if (tid < 256) vec4[tid] = ((const float4*)(g_b + batch * NN))[tid];
    __syncthreads();
    {
        int ibase = seg * 128 + w * 4;
        const uint4* K0 = (const uint4*)(g_Kh + (size_t)(batch * NN + ibase) * NN);
        float s0 = 0.f, s1 = 0.f, s2 = 0.f, s3 = 0.f;
        #pragma unroll
        for (int k = 0; k < 4; k++) {
            int idx = k * 32 + lane;
            float4 b0 = vec4[idx * 2], b1 = vec4[idx * 2 + 1];
            s0 += dot8log(K0[          idx], b0, b1);
            s1 += dot8log(K0[128 +     idx], b0, b1);
            s2 += dot8log(K0[256 +     idx], b0, b1);
            s3 += dot8log(K0[384 +     idx], b0, b1);
        }
        #pragma unroll
        for (int o = 16; o; o >>= 1) {
            s0 += __shfl_xor_sync(0xFFFFFFFFu, s0, o);
            s1 += __shfl_xor_sync(0xFFFFFFFFu, s1, o);
            s2 += __shfl_xor_sync(0xFFFFFFFFu, s2, o);
            s3 += __shfl_xor_sync(0xFFFFFFFFu, s3, o);
        }
        if (lane == 0) {
            rsum[w * 4 + 0] = s0; rsum[w * 4 + 1] = s1;
            rsum[w * 4 + 2] = s2; rsum[w * 4 + 3] = s3;
        }
    }
    __syncthreads();
    if (tid < 128) {
        int gi = batch * NN + seg * 128 + tid;
        psum[tid] = g_a[gi] * rsum[tid];
    }
    __syncthreads();
    if (tid == 0) {
        float bsum = 0.f;
        #pragma unroll
        for (int k = 0; k < 128; k++) bsum += psum[k];
        atomicAdd(&g_cost, (double)(-EPSF * bsum));
    }
    grid_barrier();
    if (bk == 0 && tid == 0) out[0] = (float)(g_cost * (1.0 / (double)BATCH));
}

// ---------------- launch ----------------
extern "C" void kernel_launch(void* const* d_in, const int* in_sizes, int n_in,
                              void* d_out, int out_size) {
    const float* x = (const float*)d_in[0];
    const float* y = (const float*)d_in[1];
    float* out = (float*)d_out;
    (void)in_sizes; (void)n_in; (void)out_size;

    softmax_kernel<<<4096, 256>>>(x, y);   // softmax + fused init
    buildK_mma<<<4096, 256>>>();           // tf32 HMMA, bf16 K store
    sinkhorn_persistent<<<GB, TB>>>(out);  // whole Sinkhorn loop + cost + finalize
}